// round 6
// baseline (speedup 1.0000x reference)
#include <cuda_runtime.h>

// LSTM(I=13,H=64,T=5) + MLP(64->64 relu ->13), B=262144, fp32, f32x2 math.
// Round 6: register-tiled batch GEMM. CTA = 64 rows; 512 threads;
// thread tile = 4 rows x 2 neurons (8 gates) -> 16 FFMA2 per k per thread
// against 4 LDS.128. h is stored pre-duplicated ((h,h) u64) in SMEM so FFMA2
// consumes it directly; c lives in registers. x is folded into the k-loop:
// gates = [x_t | h] @ [W_ih | W_hh]^T, k = 0..76.
// Warp shape = 8 neuron-cols x 4 row-groups => w-loads ~8-distinct,
// h-loads 4-distinct per instruction (near conflict-free).

#define THREADS 512
#define ROWS 64           // batch rows per CTA
#define KTOT 77           // 13 (x) + 64 (h)
#define XH_STRIDE 66      // u64 per k-row (64 rows + 2 pad) -> 528B, 16B-aligned

typedef unsigned long long u64;

__device__ __forceinline__ u64 pack2(float a, float b) {
    u64 r; asm("mov.b64 %0, {%1, %2};" : "=l"(r) : "f"(a), "f"(b)); return r;
}
__device__ __forceinline__ u64 dup2(float a) {
    u64 r; asm("mov.b64 %0, {%1, %1};" : "=l"(r) : "f"(a)); return r;
}
__device__ __forceinline__ void unpack2(u64 v, float& a, float& b) {
    asm("mov.b64 {%0, %1}, %2;" : "=f"(a), "=f"(b) : "l"(v));
}
__device__ __forceinline__ void fma2(u64& d, u64 a, u64 b) {
    asm("fma.rn.f32x2 %0, %1, %2, %0;" : "+l"(d) : "l"(a), "l"(b));
}

__device__ __forceinline__ float fsig(float v) {
    return __fdividef(1.0f, 1.0f + __expf(-v));
}
__device__ __forceinline__ float ftanh_(float v) {
    v = fminf(fmaxf(v, -15.0f), 15.0f);
    float e = __expf(-2.0f * v);
    return __fdividef(1.0f - e, 1.0f + e);
}

// SMEM byte offsets
#define OFF_WCAT 0                                   // float4 [77][64]   78848
#define OFF_XH   (OFF_WCAT + 77*64*16)               // u64 [77][66]      40656
#define OFF_Z    (OFF_XH   + 77*66*8)                // u64 [64][66]      33792
#define OFF_W1P  (OFF_Z    + 64*66*8)                // u64 [64][32]      16384
#define OFF_W2P  (OFF_W1P  + 64*32*8)                // u64 [64][7]        3584
#define OFF_BC   (OFF_W2P  + 64*7*8)                 // float4 [64]        1024
#define OFF_B1P  (OFF_BC   + 64*16)                  // u64 [32]            256
#define OFF_B2P  (OFF_B1P  + 32*8)                   // u64 [7] (+pad)       64
#define OFF_X    (OFF_B2P  + 64)                     // float [64][65]    16640
#define SMEM_BYTES (OFF_X + 64*65*4)                 // = 191248

extern __shared__ char smem_raw[];

__global__ void __launch_bounds__(THREADS, 1)
lstm_gemm_kernel(const float* __restrict__ x,
                 const float* __restrict__ W_ih,
                 const float* __restrict__ W_hh,
                 const float* __restrict__ b_ih,
                 const float* __restrict__ b_hh,
                 const float* __restrict__ W1,
                 const float* __restrict__ b1,
                 const float* __restrict__ W2,
                 const float* __restrict__ b2,
                 float* __restrict__ out,
                 int B)
{
    float4* s_wcat = (float4*)(smem_raw + OFF_WCAT);  // [k][n] gate quads
    u64*    s_xh   = (u64*)  (smem_raw + OFF_XH);     // [k][row] dup'd operands
    u64*    s_z    = (u64*)  (smem_raw + OFF_Z);      // [zk][row] dup'd
    u64*    s_w1p  = (u64*)  (smem_raw + OFF_W1P);    // [k][jpair]
    u64*    s_w2p  = (u64*)  (smem_raw + OFF_W2P);    // [k][opair]
    float4* s_bc   = (float4*)(smem_raw + OFF_BC);    // [n] (b_ih+b_hh) quads
    u64*    s_b1p  = (u64*)  (smem_raw + OFF_B1P);
    u64*    s_b2p  = (u64*)  (smem_raw + OFF_B2P);
    float*  s_x    = (float*)(smem_raw + OFF_X);      // [row][65]

    const int tid  = threadIdx.x;
    const int lane = tid & 31;
    const int wrp  = tid >> 5;
    // warp shape: 8 neuron-cols x 4 row-groups
    const int col = (wrp & 3) * 8 + (lane & 7);   // 0..31  (2 neurons each)
    const int rg  = (wrp >> 2) * 4 + (lane >> 3); // 0..15  (4 rows each)
    const int r0  = rg * 4;
    const int n0  = col * 2;

    const int b0 = blockIdx.x * ROWS;

    // ================= stage & reorganize =================
    // gate-quad weights [k][n] : k<13 from W_ih (col k), k>=13 from W_hh (col k-13)
    for (int idx = tid; idx < 77 * 64; idx += THREADS) {
        int k = idx >> 6, n = idx & 63;
        float4 q;
        if (k < 13) {
            q.x = W_ih[(n      ) * 13 + k];
            q.y = W_ih[(n +  64) * 13 + k];
            q.z = W_ih[(n + 128) * 13 + k];
            q.w = W_ih[(n + 192) * 13 + k];
        } else {
            int kk = k - 13;
            q.x = W_hh[(n      ) * 64 + kk];
            q.y = W_hh[(n +  64) * 64 + kk];
            q.z = W_hh[(n + 128) * 64 + kk];
            q.w = W_hh[(n + 192) * 64 + kk];
        }
        s_wcat[idx] = q;
    }
    // W1 pairs [k][j]: (W1[2j][k], W1[2j+1][k])
    for (int idx = tid; idx < 64 * 32; idx += THREADS) {
        int k = idx >> 5, j = idx & 31;
        s_w1p[idx] = pack2(W1[(2 * j) * 64 + k], W1[(2 * j + 1) * 64 + k]);
    }
    // W2 pairs [k][op]: (W2[2op][k], W2[2op+1][k] or 0)
    for (int idx = tid; idx < 64 * 7; idx += THREADS) {
        int k = idx / 7, op = idx % 7;
        float lo = W2[(2 * op) * 64 + k];
        float hi = (2 * op + 1 < 13) ? W2[(2 * op + 1) * 64 + k] : 0.0f;
        s_w2p[idx] = pack2(lo, hi);
    }
    if (tid < 64) {
        float4 v;
        v.x = b_ih[tid]       + b_hh[tid];
        v.y = b_ih[tid + 64]  + b_hh[tid + 64];
        v.z = b_ih[tid + 128] + b_hh[tid + 128];
        v.w = b_ih[tid + 192] + b_hh[tid + 192];
        s_bc[tid] = v;
    }
    if (tid < 32) s_b1p[tid] = pack2(b1[2 * tid], b1[2 * tid + 1]);
    if (tid < 7)  s_b2p[tid] = pack2(b2[2 * tid],
                                     (2 * tid + 1 < 13) ? b2[2 * tid + 1] : 0.0f);
    // prefetch this CTA's x rows (coalesced)
    {
        const float* xg = x + (size_t)b0 * 65;
        for (int idx = tid; idx < ROWS * 65; idx += THREADS) s_x[idx] = xg[idx];
    }
    // zero h-region of XH
    for (int idx = tid; idx < 64 * XH_STRIDE; idx += THREADS)
        s_xh[13 * XH_STRIDE + idx] = 0ULL;
    __syncthreads();

    // x(0) dup into XH rows 0..12
    for (int idx = tid; idx < 13 * 64; idx += THREADS) {
        int i = idx >> 6, row = idx & 63;
        s_xh[i * XH_STRIDE + row] = dup2(s_x[row * 65 + i]);
    }
    __syncthreads();

    // ================= recurrence =================
    float c[8];
#pragma unroll
    for (int j = 0; j < 8; j++) c[j] = 0.0f;

    u64 aif[8], ago[8];   // index = jrow*2 + m(neuron)

#pragma unroll 1
    for (int t = 0; t < 5; t++) {
        float4 q0 = s_bc[n0], q1 = s_bc[n0 + 1];
        u64 bif0 = pack2(q0.x, q0.y), bgo0 = pack2(q0.z, q0.w);
        u64 bif1 = pack2(q1.x, q1.y), bgo1 = pack2(q1.z, q1.w);
#pragma unroll
        for (int j = 0; j < 4; j++) {
            aif[j * 2 + 0] = bif0; ago[j * 2 + 0] = bgo0;
            aif[j * 2 + 1] = bif1; ago[j * 2 + 1] = bgo1;
        }

        const float4* wp = s_wcat + n0;
        const u64*    hp = s_xh + r0;
#pragma unroll 7
        for (int k = 0; k < KTOT; k++) {
            ulonglong2 w0 = *(const ulonglong2*)(wp + (size_t)k * 64);
            ulonglong2 w1 = *(const ulonglong2*)(wp + (size_t)k * 64 + 1);
            ulonglong2 ha = *(const ulonglong2*)(hp + (size_t)k * XH_STRIDE);
            ulonglong2 hb = *(const ulonglong2*)(hp + (size_t)k * XH_STRIDE + 2);
            fma2(aif[0], w0.x, ha.x); fma2(ago[0], w0.y, ha.x);
            fma2(aif[1], w1.x, ha.x); fma2(ago[1], w1.y, ha.x);
            fma2(aif[2], w0.x, ha.y); fma2(ago[2], w0.y, ha.y);
            fma2(aif[3], w1.x, ha.y); fma2(ago[3], w1.y, ha.y);
            fma2(aif[4], w0.x, hb.x); fma2(ago[4], w0.y, hb.x);
            fma2(aif[5], w1.x, hb.x); fma2(ago[5], w1.y, hb.x);
            fma2(aif[6], w0.x, hb.y); fma2(ago[6], w0.y, hb.y);
            fma2(aif[7], w1.x, hb.y); fma2(ago[7], w1.y, hb.y);
        }
        __syncthreads();   // all XH reads done before h rewrites

        // epilogue: activations, c update, write dup'd h
#pragma unroll
        for (int j = 0; j < 4; j++) {
#pragma unroll
            for (int m = 0; m < 2; m++) {
                float ai, af, ag, ao;
                unpack2(aif[j * 2 + m], ai, af);
                unpack2(ago[j * 2 + m], ag, ao);
                float cn = fsig(af) * c[j * 2 + m] + fsig(ai) * ftanh_(ag);
                c[j * 2 + m] = cn;
                float hn = fsig(ao) * ftanh_(cn);
                s_xh[(13 + n0 + m) * XH_STRIDE + r0 + j] = dup2(hn);
            }
        }
        // write x(t+1) dup
        if (t < 4) {
            for (int idx = tid; idx < 13 * 64; idx += THREADS) {
                int i = idx >> 6, row = idx & 63;
                s_xh[i * XH_STRIDE + row] = dup2(s_x[row * 65 + (t + 1) * 13 + i]);
            }
        }
        __syncthreads();
    }

    // ================= MLP layer 1 =================
    // thread: output pair j = col (outputs 2j, 2j+1), rows r0..r0+3
    {
        u64 z2[4];
        u64 bv = s_b1p[col];
#pragma unroll
        for (int j = 0; j < 4; j++) z2[j] = bv;

        const u64* hp = s_xh + 13 * XH_STRIDE + r0;
#pragma unroll 8
        for (int k = 0; k < 64; k++) {
            u64 wv = s_w1p[k * 32 + col];
            ulonglong2 ha = *(const ulonglong2*)(hp + (size_t)k * XH_STRIDE);
            ulonglong2 hb = *(const ulonglong2*)(hp + (size_t)k * XH_STRIDE + 2);
            fma2(z2[0], wv, ha.x);
            fma2(z2[1], wv, ha.y);
            fma2(z2[2], wv, hb.x);
            fma2(z2[3], wv, hb.y);
        }
#pragma unroll
        for (int j = 0; j < 4; j++) {
            float za, zb;
            unpack2(z2[j], za, zb);
            za = fmaxf(za, 0.0f);
            zb = fmaxf(zb, 0.0f);
            s_z[(2 * col    ) * XH_STRIDE + r0 + j] = dup2(za);
            s_z[(2 * col + 1) * XH_STRIDE + r0 + j] = dup2(zb);
        }
    }
    __syncthreads();

    // ================= MLP layer 2 =================
    if (tid < 448) {
        int row = tid / 7, op = tid % 7;
        u64 acc = s_b2p[op];
#pragma unroll 8
        for (int k = 0; k < 64; k++)
            fma2(acc, s_w2p[k * 7 + op], s_z[k * XH_STRIDE + row]);
        float oa, ob;
        unpack2(acc, oa, ob);
        float* op_ptr = out + (size_t)(b0 + row) * 13;
        op_ptr[2 * op] = oa;
        if (2 * op + 1 < 13) op_ptr[2 * op + 1] = ob;
    }
}

extern "C" void kernel_launch(void* const* d_in, const int* in_sizes, int n_in,
                              void* d_out, int out_size)
{
    const float* x    = (const float*)d_in[0];
    const float* W_ih = (const float*)d_in[1];
    const float* W_hh = (const float*)d_in[2];
    const float* b_ih = (const float*)d_in[3];
    const float* b_hh = (const float*)d_in[4];
    const float* W1   = (const float*)d_in[5];
    const float* b1   = (const float*)d_in[6];
    const float* W2   = (const float*)d_in[7];
    const float* b2   = (const float*)d_in[8];
    float* out = (float*)d_out;

    const int B = in_sizes[0] / 65;

    cudaFuncSetAttribute(lstm_gemm_kernel,
                         cudaFuncAttributeMaxDynamicSharedMemorySize, SMEM_BYTES);

    const int grid = (B + ROWS - 1) / ROWS;
    lstm_gemm_kernel<<<grid, THREADS, SMEM_BYTES>>>(
        x, W_ih, W_hh, b_ih, b_hh, W1, b1, W2, b2, out, B);
}

// round 8
// speedup vs baseline: 2.0844x; 2.0844x over previous
#include <cuda_runtime.h>
#include <cuda_bf16.h>
#include <cstdint>

// LSTM(I=13,H=64,T=5)+MLP(64->64 relu ->13), B=262144.
// Round 8: warp-level mma.sync bf16 (HMMA, sm_80 ISA - works on compute_103
// target) with hi/lo split fp32 emulation: P = Ah*Wh + Ah*Wl + Al*Wh.
// CTA = 64 batch rows, 256 threads (8 warps). Warp tile = 64 rows x 32 cols
// (8 neurons x 4 gates, col order C = 4*neuron + gate). Weight fragments
// live in registers across all 5 timesteps; A (=[h|x], K=80) streamed from
// SMEM via conflict-free LDS.32 fragment loads. Cell state c in registers.
// Gate exchange via one shfl.xor(1). MLP layers reuse the same mma path.

#define THREADS 256
#define CTA_ROWS 64
#define WSTR 88   // halves per row for W/A arrays (176B, 16B aligned)
#define ZSTR 72   // halves per row for Z array

// byte offsets in dynamic smem
#define OFF_WHI   0         // [256][88] bf16 : 45056
#define OFF_WLO   45056
#define OFF_AHI   90112     // [64][88] bf16  : 11264
#define OFF_ALO   101376
#define OFF_W1HI  112640    // [64][88] bf16  : 11264
#define OFF_W1LO  123904
#define OFF_W2HI  135168    // [16][88] bf16  : 2816
#define OFF_W2LO  137984
#define OFF_ZHI   140800    // [64][72] bf16  : 9216
#define OFF_ZLO   150016
#define OFF_BC    159232    // float [256]
#define OFF_B1    160256    // float [64]
#define OFF_B2    160512    // float [16]
#define SMEM_BYTES 160576

__device__ __forceinline__ void mma16816(float* d,
    uint32_t a0, uint32_t a1, uint32_t a2, uint32_t a3,
    uint32_t b0, uint32_t b1)
{
    asm volatile(
        "mma.sync.aligned.m16n8k16.row.col.f32.bf16.bf16.f32 "
        "{%0,%1,%2,%3}, {%4,%5,%6,%7}, {%8,%9}, {%0,%1,%2,%3};"
        : "+f"(d[0]), "+f"(d[1]), "+f"(d[2]), "+f"(d[3])
        : "r"(a0), "r"(a1), "r"(a2), "r"(a3), "r"(b0), "r"(b1));
}

__device__ __forceinline__ void bsplit(float v, unsigned short& h, unsigned short& l) {
    __nv_bfloat16 hb = __float2bfloat16(v);
    __nv_bfloat16 lb = __float2bfloat16(v - __bfloat162float(hb));
    h = __bfloat16_as_ushort(hb);
    l = __bfloat16_as_ushort(lb);
}

__device__ __forceinline__ float fsig(float v) {
    return __fdividef(1.0f, 1.0f + __expf(-v));
}
__device__ __forceinline__ float ftanh_(float v) {
    v = fminf(fmaxf(v, -15.0f), 15.0f);
    float e = __expf(-2.0f * v);
    return __fdividef(1.0f - e, 1.0f + e);
}

extern __shared__ char smem_raw[];

__global__ void __launch_bounds__(THREADS, 1)
lstm_hmma_kernel(const float* __restrict__ x,
                 const float* __restrict__ W_ih,
                 const float* __restrict__ W_hh,
                 const float* __restrict__ b_ih,
                 const float* __restrict__ b_hh,
                 const float* __restrict__ W1,
                 const float* __restrict__ b1,
                 const float* __restrict__ W2,
                 const float* __restrict__ b2,
                 float* __restrict__ out,
                 int B)
{
    unsigned short* sW_hi  = (unsigned short*)(smem_raw + OFF_WHI);
    unsigned short* sW_lo  = (unsigned short*)(smem_raw + OFF_WLO);
    unsigned short* sA_hi  = (unsigned short*)(smem_raw + OFF_AHI);
    unsigned short* sA_lo  = (unsigned short*)(smem_raw + OFF_ALO);
    unsigned short* sW1_hi = (unsigned short*)(smem_raw + OFF_W1HI);
    unsigned short* sW1_lo = (unsigned short*)(smem_raw + OFF_W1LO);
    unsigned short* sW2_hi = (unsigned short*)(smem_raw + OFF_W2HI);
    unsigned short* sW2_lo = (unsigned short*)(smem_raw + OFF_W2LO);
    unsigned short* sZ_hi  = (unsigned short*)(smem_raw + OFF_ZHI);
    unsigned short* sZ_lo  = (unsigned short*)(smem_raw + OFF_ZLO);
    const uint32_t* W_hi32  = (const uint32_t*)sW_hi;
    const uint32_t* W_lo32  = (const uint32_t*)sW_lo;
    const uint32_t* A_hi32  = (const uint32_t*)sA_hi;
    const uint32_t* A_lo32  = (const uint32_t*)sA_lo;
    const uint32_t* W1_hi32 = (const uint32_t*)sW1_hi;
    const uint32_t* W1_lo32 = (const uint32_t*)sW1_lo;
    const uint32_t* W2_hi32 = (const uint32_t*)sW2_hi;
    const uint32_t* W2_lo32 = (const uint32_t*)sW2_lo;
    const uint32_t* Z_hi32  = (const uint32_t*)sZ_hi;
    const uint32_t* Z_lo32  = (const uint32_t*)sZ_lo;
    float* s_bc = (float*)(smem_raw + OFF_BC);
    float* s_b1 = (float*)(smem_raw + OFF_B1);
    float* s_b2 = (float*)(smem_raw + OFF_B2);

    const int tid  = threadIdx.x;
    const int lane = tid & 31;
    const int w    = tid >> 5;      // warp 0..7
    const int g    = lane >> 2;     // 0..7
    const int c    = lane & 3;      // 0..3
    const bool odd = (c & 1);
    const int b0   = blockIdx.x * CTA_ROWS;

    // ---------------- stage weights (bf16 hi/lo) ----------------
    // gates weight: col C = 4*neuron + gate ; original row R = 64*gate + neuron
    // k<64: W_hh ; 64..76: W_ih ; 77..79: 0
    for (int idx = tid; idx < 256 * 80; idx += THREADS) {
        int C = idx / 80, k = idx % 80;
        int R = 64 * (C & 3) + (C >> 2);
        float v = 0.0f;
        if (k < 64)      v = W_hh[R * 64 + k];
        else if (k < 77) v = W_ih[R * 13 + (k - 64)];
        unsigned short h, l; bsplit(v, h, l);
        sW_hi[C * WSTR + k] = h;
        sW_lo[C * WSTR + k] = l;
    }
    for (int idx = tid; idx < 64 * 64; idx += THREADS) {
        int j = idx >> 6, k = idx & 63;
        unsigned short h, l; bsplit(W1[j * 64 + k], h, l);
        sW1_hi[j * WSTR + k] = h;
        sW1_lo[j * WSTR + k] = l;
    }
    for (int idx = tid; idx < 16 * 64; idx += THREADS) {
        int p = idx >> 6, k = idx & 63;
        float v = (p < 13) ? W2[p * 64 + k] : 0.0f;
        unsigned short h, l; bsplit(v, h, l);
        sW2_hi[p * WSTR + k] = h;
        sW2_lo[p * WSTR + k] = l;
    }
    for (int idx = tid; idx < 256; idx += THREADS) {
        int R = 64 * (idx & 3) + (idx >> 2);
        s_bc[idx] = b_ih[R] + b_hh[R];
    }
    if (tid < 64) s_b1[tid] = b1[tid];
    if (tid < 16) s_b2[tid] = (tid < 13) ? b2[tid] : 0.0f;

    // zero A arrays (h part = h0 = 0, pads stay 0)
    {
        uint32_t* Ah = (uint32_t*)sA_hi;
        uint32_t* Al = (uint32_t*)sA_lo;
        for (int idx = tid; idx < 64 * (WSTR / 2); idx += THREADS) {
            Ah[idx] = 0; Al[idx] = 0;
        }
    }
    __syncthreads();

    // x(t=0) into A at k = 64+i
    for (int idx = tid; idx < CTA_ROWS * 13; idx += THREADS) {
        int r = idx / 13, i = idx % 13;
        unsigned short h, l; bsplit(x[(size_t)(b0 + r) * 65 + i], h, l);
        sA_hi[r * WSTR + 64 + i] = h;
        sA_lo[r * WSTR + 64 + i] = l;
    }

    // ---------------- resident B fragments ----------------
    uint32_t bh[4][5][2], bl[4][5][2];
#pragma unroll
    for (int ct = 0; ct < 4; ct++) {
#pragma unroll
        for (int kc = 0; kc < 5; kc++) {
            int widx = (32 * w + 8 * ct + g) * (WSTR / 2) + 8 * kc + c;
            bh[ct][kc][0] = W_hi32[widx];
            bh[ct][kc][1] = W_hi32[widx + 4];
            bl[ct][kc][0] = W_lo32[widx];
            bl[ct][kc][1] = W_lo32[widx + 4];
        }
    }
    float bcx[4], bcy[4];
#pragma unroll
    for (int ct = 0; ct < 4; ct++) {
        int C0 = 32 * w + 8 * ct + 2 * c;
        bcx[ct] = s_bc[C0];
        bcy[ct] = s_bc[C0 + 1];
    }

    float creg[16];
#pragma unroll
    for (int i = 0; i < 16; i++) creg[i] = 0.0f;

    __syncthreads();

    // ---------------- 5 recurrent steps ----------------
#pragma unroll 1
    for (int t = 0; t < 5; t++) {
        // prefetch x(t+1)
        float xf[4];
        if (t < 4) {
#pragma unroll
            for (int s = 0; s < 4; s++) {
                int idx = tid + s * THREADS;
                if (idx < CTA_ROWS * 13) {
                    int r = idx / 13, i = idx % 13;
                    xf[s] = x[(size_t)(b0 + r) * 65 + (t + 1) * 13 + i];
                }
            }
        }

        float d[4][4][4];
#pragma unroll
        for (int rt = 0; rt < 4; rt++)
#pragma unroll
            for (int ct = 0; ct < 4; ct++) {
                d[rt][ct][0] = bcx[ct]; d[rt][ct][1] = bcy[ct];
                d[rt][ct][2] = bcx[ct]; d[rt][ct][3] = bcy[ct];
            }

#pragma unroll
        for (int kc = 0; kc < 5; kc++) {
#pragma unroll
            for (int rt = 0; rt < 4; rt++) {
                int r0w = (16 * rt + g) * (WSTR / 2) + 8 * kc + c;
                int r1w = r0w + 8 * (WSTR / 2);
                uint32_t ah0 = A_hi32[r0w],     ah1 = A_hi32[r1w];
                uint32_t ah2 = A_hi32[r0w + 4], ah3 = A_hi32[r1w + 4];
                uint32_t al0 = A_lo32[r0w],     al1 = A_lo32[r1w];
                uint32_t al2 = A_lo32[r0w + 4], al3 = A_lo32[r1w + 4];
#pragma unroll
                for (int ct = 0; ct < 4; ct++) {
                    mma16816(d[rt][ct], ah0, ah1, ah2, ah3, bh[ct][kc][0], bh[ct][kc][1]);
                    mma16816(d[rt][ct], ah0, ah1, ah2, ah3, bl[ct][kc][0], bl[ct][kc][1]);
                    mma16816(d[rt][ct], al0, al1, al2, al3, bh[ct][kc][0], bh[ct][kc][1]);
                }
            }
        }
        __syncthreads();   // all A reads complete before h rewrite

        // epilogue: gate exchange + activations + h write
#pragma unroll
        for (int rt = 0; rt < 4; rt++) {
#pragma unroll
            for (int ct = 0; ct < 4; ct++) {
                float d0 = d[rt][ct][0], d1 = d[rt][ct][1];
                float d2 = d[rt][ct][2], d3 = d[rt][ct][3];
                float e0 = __shfl_xor_sync(0xffffffffu, d0, 1);
                float e1 = __shfl_xor_sync(0xffffffffu, d1, 1);
                float e2 = __shfl_xor_sync(0xffffffffu, d2, 1);
                float e3 = __shfl_xor_sync(0xffffffffu, d3, 1);
                float gi = odd ? e2 : d0;
                float gf = odd ? e3 : d1;
                float gg = odd ? d2 : e0;
                float go = odd ? d3 : e1;
                float cold = creg[rt * 4 + ct];
                float cn = fsig(gf) * cold + fsig(gi) * ftanh_(gg);
                creg[rt * 4 + ct] = cn;
                float hv = fsig(go) * ftanh_(cn);
                int row = 16 * rt + g + (odd ? 8 : 0);
                int n   = 8 * w + 2 * ct + (c >> 1);
                unsigned short h, l; bsplit(hv, h, l);
                sA_hi[row * WSTR + n] = h;
                sA_lo[row * WSTR + n] = l;
            }
        }

        if (t < 4) {
#pragma unroll
            for (int s = 0; s < 4; s++) {
                int idx = tid + s * THREADS;
                if (idx < CTA_ROWS * 13) {
                    int r = idx / 13, i = idx % 13;
                    unsigned short h, l; bsplit(xf[s], h, l);
                    sA_hi[r * WSTR + 64 + i] = h;
                    sA_lo[r * WSTR + 64 + i] = l;
                }
            }
        }
        __syncthreads();
    }

    // ---------------- MLP layer 1 via mma: z = relu(h @ W1^T + b1) ----------------
    {
        uint32_t b1h[4][2], b1l[4][2];
#pragma unroll
        for (int kc = 0; kc < 4; kc++) {
            int widx = (8 * w + g) * (WSTR / 2) + 8 * kc + c;
            b1h[kc][0] = W1_hi32[widx]; b1h[kc][1] = W1_hi32[widx + 4];
            b1l[kc][0] = W1_lo32[widx]; b1l[kc][1] = W1_lo32[widx + 4];
        }
        int col0 = 8 * w + 2 * c;
        float dz[4][4];
#pragma unroll
        for (int rt = 0; rt < 4; rt++) {
            dz[rt][0] = s_b1[col0]; dz[rt][1] = s_b1[col0 + 1];
            dz[rt][2] = s_b1[col0]; dz[rt][3] = s_b1[col0 + 1];
        }
#pragma unroll
        for (int kc = 0; kc < 4; kc++) {
#pragma unroll
            for (int rt = 0; rt < 4; rt++) {
                int r0w = (16 * rt + g) * (WSTR / 2) + 8 * kc + c;
                int r1w = r0w + 8 * (WSTR / 2);
                uint32_t ah0 = A_hi32[r0w],     ah1 = A_hi32[r1w];
                uint32_t ah2 = A_hi32[r0w + 4], ah3 = A_hi32[r1w + 4];
                uint32_t al0 = A_lo32[r0w],     al1 = A_lo32[r1w];
                uint32_t al2 = A_lo32[r0w + 4], al3 = A_lo32[r1w + 4];
                mma16816(dz[rt], ah0, ah1, ah2, ah3, b1h[kc][0], b1h[kc][1]);
                mma16816(dz[rt], ah0, ah1, ah2, ah3, b1l[kc][0], b1l[kc][1]);
                mma16816(dz[rt], al0, al1, al2, al3, b1h[kc][0], b1h[kc][1]);
            }
        }
#pragma unroll
        for (int rt = 0; rt < 4; rt++) {
            int rA = 16 * rt + g, rB = rA + 8;
            unsigned short h, l;
            bsplit(fmaxf(dz[rt][0], 0.0f), h, l);
            sZ_hi[rA * ZSTR + col0] = h;     sZ_lo[rA * ZSTR + col0] = l;
            bsplit(fmaxf(dz[rt][1], 0.0f), h, l);
            sZ_hi[rA * ZSTR + col0 + 1] = h; sZ_lo[rA * ZSTR + col0 + 1] = l;
            bsplit(fmaxf(dz[rt][2], 0.0f), h, l);
            sZ_hi[rB * ZSTR + col0] = h;     sZ_lo[rB * ZSTR + col0] = l;
            bsplit(fmaxf(dz[rt][3], 0.0f), h, l);
            sZ_hi[rB * ZSTR + col0 + 1] = h; sZ_lo[rB * ZSTR + col0 + 1] = l;
        }
    }
    __syncthreads();

    // ---------------- MLP layer 2 via mma: out = z @ W2^T + b2 ----------------
    {
        int rt2 = w >> 1, ct2 = w & 1;   // warp -> (rowtile, coltile of 16 cols)
        uint32_t b2h[4][2], b2l[4][2];
#pragma unroll
        for (int kc = 0; kc < 4; kc++) {
            int widx = (8 * ct2 + g) * (WSTR / 2) + 8 * kc + c;
            b2h[kc][0] = W2_hi32[widx]; b2h[kc][1] = W2_hi32[widx + 4];
            b2l[kc][0] = W2_lo32[widx]; b2l[kc][1] = W2_lo32[widx + 4];
        }
        int colA = 8 * ct2 + 2 * c, colB = colA + 1;
        float dd[4];
        dd[0] = s_b2[colA]; dd[1] = s_b2[colB];
        dd[2] = s_b2[colA]; dd[3] = s_b2[colB];
#pragma unroll
        for (int kc = 0; kc < 4; kc++) {
            int r0w = (16 * rt2 + g) * (ZSTR / 2) + 8 * kc + c;
            int r1w = r0w + 8 * (ZSTR / 2);
            uint32_t ah0 = Z_hi32[r0w],     ah1 = Z_hi32[r1w];
            uint32_t ah2 = Z_hi32[r0w + 4], ah3 = Z_hi32[r1w + 4];
            uint32_t al0 = Z_lo32[r0w],     al1 = Z_lo32[r1w];
            uint32_t al2 = Z_lo32[r0w + 4], al3 = Z_lo32[r1w + 4];
            mma16816(dd, ah0, ah1, ah2, ah3, b2h[kc][0], b2h[kc][1]);
            mma16816(dd, ah0, ah1, ah2, ah3, b2l[kc][0], b2l[kc][1]);
            mma16816(dd, al0, al1, al2, al3, b2h[kc][0], b2h[kc][1]);
        }
        int rowA = 16 * rt2 + g, rowB = rowA + 8;
        if (colA < 13) {
            out[(size_t)(b0 + rowA) * 13 + colA] = dd[0];
            out[(size_t)(b0 + rowB) * 13 + colA] = dd[2];
        }
        if (colB < 13) {
            out[(size_t)(b0 + rowA) * 13 + colB] = dd[1];
            out[(size_t)(b0 + rowB) * 13 + colB] = dd[3];
        }
    }
}

extern "C" void kernel_launch(void* const* d_in, const int* in_sizes, int n_in,
                              void* d_out, int out_size)
{
    const float* x    = (const float*)d_in[0];
    const float* W_ih = (const float*)d_in[1];
    const float* W_hh = (const float*)d_in[2];
    const float* b_ih = (const float*)d_in[3];
    const float* b_hh = (const float*)d_in[4];
    const float* W1   = (const float*)d_in[5];
    const float* b1   = (const float*)d_in[6];
    const float* W2   = (const float*)d_in[7];
    const float* b2   = (const float*)d_in[8];
    float* out = (float*)d_out;

    const int B = in_sizes[0] / 65;

    cudaFuncSetAttribute(lstm_hmma_kernel,
                         cudaFuncAttributeMaxDynamicSharedMemorySize, SMEM_BYTES);

    const int grid = B / CTA_ROWS;
    lstm_hmma_kernel<<<grid, THREADS, SMEM_BYTES>>>(
        x, W_ih, W_hh, b_ih, b_hh, W1, b1, W2, b2, out, B);
}

// round 9
// speedup vs baseline: 3.0671x; 1.4715x over previous
#include <cuda_runtime.h>
#include <cuda_bf16.h>
#include <cstdint>

// LSTM(I=13,H=64,T=5)+MLP(64->64 relu ->13), B=262144.
// Round 9: mma.sync bf16 hi/lo (3-product fp32 emulation) as R8, but:
//  - 512 threads / CTA, CTA_ROWS=128 -> 16 warps/SM (4 per SMSP)
//  - warp tile 64 rows x 32 cols processed in TWO passes of 16 cols so the
//    accumulator footprint halves (d[4][2][4]); pass-0 h values parked in
//    8 regs until both passes' A reads complete, then one deferred STS phase.
//  - B fragments reloaded from SMEM per k-chunk (saves 40 regs).
// Weights gate-reordered col C = 4*neuron + gate; gate exchange via shfl.xor(1).
// MLP layers also run on mma. Cell state c in registers.

#define THREADS 512
#define CTA_ROWS 128
#define WSTR 88   // halves per k-row (176B)
#define WSTR32 44
#define ZSTR 72
#define ZSTR32 36

// byte offsets in dynamic smem
#define OFF_WHI   0         // [256][88] bf16 : 45056
#define OFF_WLO   45056
#define OFF_AHI   90112     // [128][88] bf16 : 22528
#define OFF_ALO   112640
#define OFF_W1HI  135168    // [64][88] bf16  : 11264
#define OFF_W1LO  146432
#define OFF_W2HI  157696    // [16][88] bf16  : 2816
#define OFF_W2LO  160512
#define OFF_ZHI   163328    // [128][72] bf16 : 18432
#define OFF_ZLO   181760
#define OFF_BC    200192    // float [256]
#define OFF_B1    201216    // float [64]
#define OFF_B2    201472    // float [16]
#define SMEM_BYTES 201536

__device__ __forceinline__ void mma16816(float* d,
    uint32_t a0, uint32_t a1, uint32_t a2, uint32_t a3,
    uint32_t b0, uint32_t b1)
{
    asm volatile(
        "mma.sync.aligned.m16n8k16.row.col.f32.bf16.bf16.f32 "
        "{%0,%1,%2,%3}, {%4,%5,%6,%7}, {%8,%9}, {%0,%1,%2,%3};"
        : "+f"(d[0]), "+f"(d[1]), "+f"(d[2]), "+f"(d[3])
        : "r"(a0), "r"(a1), "r"(a2), "r"(a3), "r"(b0), "r"(b1));
}

__device__ __forceinline__ void bsplit(float v, unsigned short& h, unsigned short& l) {
    __nv_bfloat16 hb = __float2bfloat16(v);
    __nv_bfloat16 lb = __float2bfloat16(v - __bfloat162float(hb));
    h = __bfloat16_as_ushort(hb);
    l = __bfloat16_as_ushort(lb);
}

__device__ __forceinline__ float fsig(float v) {
    return __fdividef(1.0f, 1.0f + __expf(-v));
}
__device__ __forceinline__ float ftanh_(float v) {
    v = fminf(fmaxf(v, -15.0f), 15.0f);
    float e = __expf(-2.0f * v);
    return __fdividef(1.0f - e, 1.0f + e);
}

extern __shared__ char smem_raw[];

__global__ void __launch_bounds__(THREADS, 1)
lstm_hmma2_kernel(const float* __restrict__ x,
                  const float* __restrict__ W_ih,
                  const float* __restrict__ W_hh,
                  const float* __restrict__ b_ih,
                  const float* __restrict__ b_hh,
                  const float* __restrict__ W1,
                  const float* __restrict__ b1,
                  const float* __restrict__ W2,
                  const float* __restrict__ b2,
                  float* __restrict__ out,
                  int B)
{
    unsigned short* sW_hi  = (unsigned short*)(smem_raw + OFF_WHI);
    unsigned short* sW_lo  = (unsigned short*)(smem_raw + OFF_WLO);
    unsigned short* sA_hi  = (unsigned short*)(smem_raw + OFF_AHI);
    unsigned short* sA_lo  = (unsigned short*)(smem_raw + OFF_ALO);
    unsigned short* sW1_hi = (unsigned short*)(smem_raw + OFF_W1HI);
    unsigned short* sW1_lo = (unsigned short*)(smem_raw + OFF_W1LO);
    unsigned short* sW2_hi = (unsigned short*)(smem_raw + OFF_W2HI);
    unsigned short* sW2_lo = (unsigned short*)(smem_raw + OFF_W2LO);
    unsigned short* sZ_hi  = (unsigned short*)(smem_raw + OFF_ZHI);
    unsigned short* sZ_lo  = (unsigned short*)(smem_raw + OFF_ZLO);
    const uint32_t* W_hi32  = (const uint32_t*)sW_hi;
    const uint32_t* W_lo32  = (const uint32_t*)sW_lo;
    const uint32_t* A_hi32  = (const uint32_t*)sA_hi;
    const uint32_t* A_lo32  = (const uint32_t*)sA_lo;
    const uint32_t* W1_hi32 = (const uint32_t*)sW1_hi;
    const uint32_t* W1_lo32 = (const uint32_t*)sW1_lo;
    const uint32_t* W2_hi32 = (const uint32_t*)sW2_hi;
    const uint32_t* W2_lo32 = (const uint32_t*)sW2_lo;
    const uint32_t* Z_hi32  = (const uint32_t*)sZ_hi;
    const uint32_t* Z_lo32  = (const uint32_t*)sZ_lo;
    float* s_bc = (float*)(smem_raw + OFF_BC);
    float* s_b1 = (float*)(smem_raw + OFF_B1);
    float* s_b2 = (float*)(smem_raw + OFF_B2);

    const int tid  = threadIdx.x;
    const int lane = tid & 31;
    const int w    = tid >> 5;      // warp 0..15
    const int g    = lane >> 2;     // 0..7
    const int c    = lane & 3;      // 0..3
    const bool odd = (c & 1);
    const int rg   = w >> 3;        // row group 0..1 (64 rows each)
    const int cg   = w & 7;         // col group 0..7 (32 cols each)
    const int b0   = blockIdx.x * CTA_ROWS;

    // ---------------- stage weights (bf16 hi/lo) ----------------
    for (int idx = tid; idx < 256 * 80; idx += THREADS) {
        int C = idx / 80, k = idx % 80;
        int R = 64 * (C & 3) + (C >> 2);
        float v = 0.0f;
        if (k < 64)      v = W_hh[R * 64 + k];
        else if (k < 77) v = W_ih[R * 13 + (k - 64)];
        unsigned short h, l; bsplit(v, h, l);
        sW_hi[C * WSTR + k] = h;
        sW_lo[C * WSTR + k] = l;
    }
    for (int idx = tid; idx < 64 * 64; idx += THREADS) {
        int j = idx >> 6, k = idx & 63;
        unsigned short h, l; bsplit(W1[j * 64 + k], h, l);
        sW1_hi[j * WSTR + k] = h;
        sW1_lo[j * WSTR + k] = l;
    }
    for (int idx = tid; idx < 16 * 64; idx += THREADS) {
        int p = idx >> 6, k = idx & 63;
        float v = (p < 13) ? W2[p * 64 + k] : 0.0f;
        unsigned short h, l; bsplit(v, h, l);
        sW2_hi[p * WSTR + k] = h;
        sW2_lo[p * WSTR + k] = l;
    }
    for (int idx = tid; idx < 256; idx += THREADS) {
        int R = 64 * (idx & 3) + (idx >> 2);
        s_bc[idx] = b_ih[R] + b_hh[R];
    }
    if (tid < 64) s_b1[tid] = b1[tid];
    if (tid < 16) s_b2[tid] = (tid < 13) ? b2[tid] : 0.0f;

    // zero A arrays (h part = h0 = 0, pads stay 0)
    {
        uint32_t* Ah = (uint32_t*)sA_hi;
        uint32_t* Al = (uint32_t*)sA_lo;
        for (int idx = tid; idx < CTA_ROWS * WSTR32; idx += THREADS) {
            Ah[idx] = 0; Al[idx] = 0;
        }
    }
    __syncthreads();

    // x(t=0) into A at k = 64+i
    for (int idx = tid; idx < CTA_ROWS * 13; idx += THREADS) {
        int r = idx / 13, i = idx % 13;
        unsigned short h, l; bsplit(x[(size_t)(b0 + r) * 65 + i], h, l);
        sA_hi[r * WSTR + 64 + i] = h;
        sA_lo[r * WSTR + 64 + i] = l;
    }

    float creg[16];
#pragma unroll
    for (int i = 0; i < 16; i++) creg[i] = 0.0f;

    __syncthreads();

    // ---------------- 5 recurrent steps ----------------
#pragma unroll 1
    for (int t = 0; t < 5; t++) {
        // prefetch x(t+1)
        float xf[4];
        if (t < 4) {
#pragma unroll
            for (int s = 0; s < 4; s++) {
                int idx = tid + s * THREADS;
                if (idx < CTA_ROWS * 13) {
                    int r = idx / 13, i = idx % 13;
                    xf[s] = x[(size_t)(b0 + r) * 65 + (t + 1) * 13 + i];
                }
            }
        }

        float hv[16];   // h values (pass*8 + rt*2 + ct)

#pragma unroll
        for (int p = 0; p < 2; p++) {
            float d[4][2][4];
#pragma unroll
            for (int ct = 0; ct < 2; ct++) {
                int C0 = 32 * cg + 16 * p + 8 * ct + 2 * c;
                float bx = s_bc[C0], by = s_bc[C0 + 1];
#pragma unroll
                for (int rt = 0; rt < 4; rt++) {
                    d[rt][ct][0] = bx; d[rt][ct][1] = by;
                    d[rt][ct][2] = bx; d[rt][ct][3] = by;
                }
            }

#pragma unroll
            for (int kc = 0; kc < 5; kc++) {
                uint32_t bh[2][2], bl[2][2];
#pragma unroll
                for (int ct = 0; ct < 2; ct++) {
                    int widx = (32 * cg + 16 * p + 8 * ct + g) * WSTR32 + 8 * kc + c;
                    bh[ct][0] = W_hi32[widx]; bh[ct][1] = W_hi32[widx + 4];
                    bl[ct][0] = W_lo32[widx]; bl[ct][1] = W_lo32[widx + 4];
                }
#pragma unroll
                for (int rt = 0; rt < 4; rt++) {
                    int r0w = (rg * 64 + 16 * rt + g) * WSTR32 + 8 * kc + c;
                    int r1w = r0w + 8 * WSTR32;
                    uint32_t ah0 = A_hi32[r0w],     ah1 = A_hi32[r1w];
                    uint32_t ah2 = A_hi32[r0w + 4], ah3 = A_hi32[r1w + 4];
                    uint32_t al0 = A_lo32[r0w],     al1 = A_lo32[r1w];
                    uint32_t al2 = A_lo32[r0w + 4], al3 = A_lo32[r1w + 4];
#pragma unroll
                    for (int ct = 0; ct < 2; ct++) {
                        mma16816(d[rt][ct], ah0, ah1, ah2, ah3, bh[ct][0], bh[ct][1]);
                        mma16816(d[rt][ct], ah0, ah1, ah2, ah3, bl[ct][0], bl[ct][1]);
                        mma16816(d[rt][ct], al0, al1, al2, al3, bh[ct][0], bh[ct][1]);
                    }
                }
            }

            // epilogue compute (no SMEM writes yet)
#pragma unroll
            for (int rt = 0; rt < 4; rt++) {
#pragma unroll
                for (int ct = 0; ct < 2; ct++) {
                    float d0 = d[rt][ct][0], d1 = d[rt][ct][1];
                    float d2 = d[rt][ct][2], d3 = d[rt][ct][3];
                    float e0 = __shfl_xor_sync(0xffffffffu, d0, 1);
                    float e1 = __shfl_xor_sync(0xffffffffu, d1, 1);
                    float e2 = __shfl_xor_sync(0xffffffffu, d2, 1);
                    float e3 = __shfl_xor_sync(0xffffffffu, d3, 1);
                    float gi = odd ? e2 : d0;
                    float gf = odd ? e3 : d1;
                    float gg = odd ? d2 : e0;
                    float go = odd ? d3 : e1;
                    int ci = p * 8 + rt * 2 + ct;
                    float cn = fsig(gf) * creg[ci] + fsig(gi) * ftanh_(gg);
                    creg[ci] = cn;
                    hv[ci] = fsig(go) * ftanh_(cn);
                }
            }
        }

        __syncthreads();   // all A reads (both passes, all warps) complete

        // deferred h writes
#pragma unroll
        for (int p = 0; p < 2; p++) {
#pragma unroll
            for (int rt = 0; rt < 4; rt++) {
#pragma unroll
                for (int ct = 0; ct < 2; ct++) {
                    int row = rg * 64 + 16 * rt + g + (odd ? 8 : 0);
                    int n   = 8 * cg + 4 * p + 2 * ct + (c >> 1);
                    unsigned short h, l; bsplit(hv[p * 8 + rt * 2 + ct], h, l);
                    sA_hi[row * WSTR + n] = h;
                    sA_lo[row * WSTR + n] = l;
                }
            }
        }
        if (t < 4) {
#pragma unroll
            for (int s = 0; s < 4; s++) {
                int idx = tid + s * THREADS;
                if (idx < CTA_ROWS * 13) {
                    int r = idx / 13, i = idx % 13;
                    unsigned short h, l; bsplit(xf[s], h, l);
                    sA_hi[r * WSTR + 64 + i] = h;
                    sA_lo[r * WSTR + 64 + i] = l;
                }
            }
        }
        __syncthreads();
    }

    // ---------------- MLP layer 1 via mma: z = relu(h @ W1^T + b1) ----------------
    {
        const int m_rg = w >> 3;     // 0..1 (64 rows)
        const int m_cg = w & 7;      // 0..7 (8 cols)
        int col0 = 8 * m_cg + 2 * c;
        float dz[4][4];
#pragma unroll
        for (int rt = 0; rt < 4; rt++) {
            dz[rt][0] = s_b1[col0]; dz[rt][1] = s_b1[col0 + 1];
            dz[rt][2] = s_b1[col0]; dz[rt][3] = s_b1[col0 + 1];
        }
#pragma unroll
        for (int kc = 0; kc < 4; kc++) {
            int widx = (8 * m_cg + g) * WSTR32 + 8 * kc + c;
            uint32_t b1h0 = W1_hi32[widx], b1h1 = W1_hi32[widx + 4];
            uint32_t b1l0 = W1_lo32[widx], b1l1 = W1_lo32[widx + 4];
#pragma unroll
            for (int rt = 0; rt < 4; rt++) {
                int r0w = (m_rg * 64 + 16 * rt + g) * WSTR32 + 8 * kc + c;
                int r1w = r0w + 8 * WSTR32;
                uint32_t ah0 = A_hi32[r0w],     ah1 = A_hi32[r1w];
                uint32_t ah2 = A_hi32[r0w + 4], ah3 = A_hi32[r1w + 4];
                uint32_t al0 = A_lo32[r0w],     al1 = A_lo32[r1w];
                uint32_t al2 = A_lo32[r0w + 4], al3 = A_lo32[r1w + 4];
                mma16816(dz[rt], ah0, ah1, ah2, ah3, b1h0, b1h1);
                mma16816(dz[rt], ah0, ah1, ah2, ah3, b1l0, b1l1);
                mma16816(dz[rt], al0, al1, al2, al3, b1h0, b1h1);
            }
        }
#pragma unroll
        for (int rt = 0; rt < 4; rt++) {
            int rA = m_rg * 64 + 16 * rt + g, rB = rA + 8;
            unsigned short h, l;
            bsplit(fmaxf(dz[rt][0], 0.0f), h, l);
            sZ_hi[rA * ZSTR + col0] = h;     sZ_lo[rA * ZSTR + col0] = l;
            bsplit(fmaxf(dz[rt][1], 0.0f), h, l);
            sZ_hi[rA * ZSTR + col0 + 1] = h; sZ_lo[rA * ZSTR + col0 + 1] = l;
            bsplit(fmaxf(dz[rt][2], 0.0f), h, l);
            sZ_hi[rB * ZSTR + col0] = h;     sZ_lo[rB * ZSTR + col0] = l;
            bsplit(fmaxf(dz[rt][3], 0.0f), h, l);
            sZ_hi[rB * ZSTR + col0 + 1] = h; sZ_lo[rB * ZSTR + col0 + 1] = l;
        }
    }
    __syncthreads();

    // ---------------- MLP layer 2 via mma: out = z @ W2^T + b2 ----------------
    {
        const int r2 = w >> 1;       // 0..7 (16 rows)
        const int c2 = w & 1;        // 0..1 (8 cols)
        int colA = 8 * c2 + 2 * c, colB = colA + 1;
        float dd[4];
        dd[0] = s_b2[colA]; dd[1] = s_b2[colB];
        dd[2] = s_b2[colA]; dd[3] = s_b2[colB];
#pragma unroll
        for (int kc = 0; kc < 4; kc++) {
            int widx = (8 * c2 + g) * WSTR32 + 8 * kc + c;
            uint32_t b2h0 = W2_hi32[widx], b2h1 = W2_hi32[widx + 4];
            uint32_t b2l0 = W2_lo32[widx], b2l1 = W2_lo32[widx + 4];
            int r0w = (16 * r2 + g) * ZSTR32 + 8 * kc + c;
            int r1w = r0w + 8 * ZSTR32;
            uint32_t ah0 = Z_hi32[r0w],     ah1 = Z_hi32[r1w];
            uint32_t ah2 = Z_hi32[r0w + 4], ah3 = Z_hi32[r1w + 4];
            uint32_t al0 = Z_lo32[r0w],     al1 = Z_lo32[r1w];
            uint32_t al2 = Z_lo32[r0w + 4], al3 = Z_lo32[r1w + 4];
            mma16816(dd, ah0, ah1, ah2, ah3, b2h0, b2h1);
            mma16816(dd, ah0, ah1, ah2, ah3, b2l0, b2l1);
            mma16816(dd, al0, al1, al2, al3, b2h0, b2h1);
        }
        int rowA = 16 * r2 + g, rowB = rowA + 8;
        if (colA < 13) {
            out[(size_t)(b0 + rowA) * 13 + colA] = dd[0];
            out[(size_t)(b0 + rowB) * 13 + colA] = dd[2];
        }
        if (colB < 13) {
            out[(size_t)(b0 + rowA) * 13 + colB] = dd[1];
            out[(size_t)(b0 + rowB) * 13 + colB] = dd[3];
        }
    }
}

extern "C" void kernel_launch(void* const* d_in, const int* in_sizes, int n_in,
                              void* d_out, int out_size)
{
    const float* x    = (const float*)d_in[0];
    const float* W_ih = (const float*)d_in[1];
    const float* W_hh = (const float*)d_in[2];
    const float* b_ih = (const float*)d_in[3];
    const float* b_hh = (const float*)d_in[4];
    const float* W1   = (const float*)d_in[5];
    const float* b1   = (const float*)d_in[6];
    const float* W2   = (const float*)d_in[7];
    const float* b2   = (const float*)d_in[8];
    float* out = (float*)d_out;

    const int B = in_sizes[0] / 65;

    cudaFuncSetAttribute(lstm_hmma2_kernel,
                         cudaFuncAttributeMaxDynamicSharedMemorySize, SMEM_BYTES);

    const int grid = B / CTA_ROWS;
    lstm_hmma2_kernel<<<grid, THREADS, SMEM_BYTES>>>(
        x, W_ih, W_hh, b_ih, b_hh, W1, b1, W2, b2, out, B);
}